// round 4
// baseline (speedup 1.0000x reference)
#include <cstdint>
#include <cuda_runtime.h>
#include <cuda_bf16.h>
#include <math.h>

// Shapes (fixed): B=16, T=128, L=64, D=768
#define BB 16
#define TT 128
#define LL 64
#define DD 768
#define TG 2                     // t's per attention block

__device__ float g_kfull[BB * LL * DD];
__device__ float g_ktil [BB * LL * DD];
__device__ float g_vfull[BB * LL * DD];
__device__ float g_c    [BB * LL];

// ===========================================================================
// GEMM bodies: BM=64, BN=32, BK=16, 128 threads, micro 4x4.
// NT: C[r,n] = sum_k A[r,k] * W[n,k] + bias[n]
// NN: C[r,n] = sum_k A[r,k] * W[k,n]
// ===========================================================================
__device__ __forceinline__ void gemm_nt_body(
    const float* __restrict__ A, const float* __restrict__ W,
    const float* __restrict__ bias, float* __restrict__ C,
    int row0, int col0, float (*As)[64], float (*Bs)[32], int tid)
{
    const int K = DD, N = DD;
    const int lr = tid >> 1;            // 0..63  (A row)
    const int lh = (tid & 1) * 8;       // 0/8    (A k offset)
    const int wr = tid >> 2;            // 0..31  (W row)
    const int wh = (tid & 3) * 4;       // 0..12  (W k offset)
    const int tm = (tid & 15) * 4;
    const int tn = (tid >> 4) * 4;

    float acc[4][4];
    #pragma unroll
    for (int i = 0; i < 4; i++)
        #pragma unroll
        for (int j = 0; j < 4; j++) acc[i][j] = 0.f;

    for (int k0 = 0; k0 < K; k0 += 16) {
        float4 a0 = *(const float4*)(A + (size_t)(row0 + lr) * K + k0 + lh);
        float4 a1 = *(const float4*)(A + (size_t)(row0 + lr) * K + k0 + lh + 4);
        float4 wv = *(const float4*)(W + (size_t)(col0 + wr) * K + k0 + wh);
        __syncthreads();
        As[lh + 0][lr] = a0.x; As[lh + 1][lr] = a0.y; As[lh + 2][lr] = a0.z; As[lh + 3][lr] = a0.w;
        As[lh + 4][lr] = a1.x; As[lh + 5][lr] = a1.y; As[lh + 6][lr] = a1.z; As[lh + 7][lr] = a1.w;
        Bs[wh + 0][wr] = wv.x; Bs[wh + 1][wr] = wv.y; Bs[wh + 2][wr] = wv.z; Bs[wh + 3][wr] = wv.w;
        __syncthreads();

        #pragma unroll
        for (int k = 0; k < 16; k++) {
            float4 x = *(const float4*)&As[k][tm];
            float4 y = *(const float4*)&Bs[k][tn];
            float a[4] = {x.x, x.y, x.z, x.w};
            float bcol[4] = {y.x, y.y, y.z, y.w};
            #pragma unroll
            for (int i = 0; i < 4; i++)
                #pragma unroll
                for (int j = 0; j < 4; j++)
                    acc[i][j] += a[i] * bcol[j];
        }
    }

    float4 b4 = *(const float4*)(bias + col0 + tn);
    #pragma unroll
    for (int i = 0; i < 4; i++)
        *(float4*)(C + (size_t)(row0 + tm + i) * N + col0 + tn) =
            make_float4(acc[i][0] + b4.x, acc[i][1] + b4.y,
                        acc[i][2] + b4.z, acc[i][3] + b4.w);
}

__device__ __forceinline__ void gemm_nn_body(
    const float* __restrict__ A, const float* __restrict__ W,
    float* __restrict__ C,
    int row0, int col0, float (*As)[64], float (*Bs)[32], int tid)
{
    const int K = DD, N = DD;
    const int lr = tid >> 1;
    const int lh = (tid & 1) * 8;
    const int kr = tid >> 3;            // 0..15
    const int c4 = (tid & 7) * 4;       // 0..28
    const int tm = (tid & 15) * 4;
    const int tn = (tid >> 4) * 4;

    float acc[4][4];
    #pragma unroll
    for (int i = 0; i < 4; i++)
        #pragma unroll
        for (int j = 0; j < 4; j++) acc[i][j] = 0.f;

    for (int k0 = 0; k0 < K; k0 += 16) {
        float4 a0 = *(const float4*)(A + (size_t)(row0 + lr) * K + k0 + lh);
        float4 a1 = *(const float4*)(A + (size_t)(row0 + lr) * K + k0 + lh + 4);
        float4 wv = *(const float4*)(W + (size_t)(k0 + kr) * N + col0 + c4);
        __syncthreads();
        As[lh + 0][lr] = a0.x; As[lh + 1][lr] = a0.y; As[lh + 2][lr] = a0.z; As[lh + 3][lr] = a0.w;
        As[lh + 4][lr] = a1.x; As[lh + 5][lr] = a1.y; As[lh + 6][lr] = a1.z; As[lh + 7][lr] = a1.w;
        *(float4*)&Bs[kr][c4] = wv;
        __syncthreads();

        #pragma unroll
        for (int k = 0; k < 16; k++) {
            float4 x = *(const float4*)&As[k][tm];
            float4 y = *(const float4*)&Bs[k][tn];
            float a[4] = {x.x, x.y, x.z, x.w};
            float bcol[4] = {y.x, y.y, y.z, y.w};
            #pragma unroll
            for (int i = 0; i < 4; i++)
                #pragma unroll
                for (int j = 0; j < 4; j++)
                    acc[i][j] += a[i] * bcol[j];
        }
    }

    #pragma unroll
    for (int i = 0; i < 4; i++)
        *(float4*)(C + (size_t)(row0 + tm + i) * N + col0 + tn) =
            make_float4(acc[i][0], acc[i][1], acc[i][2], acc[i][3]);
}

// keyproj: g_kfull = key @ Wk^T + bk.  grid (24, 16), 128 threads.
__global__ void __launch_bounds__(128) keyproj_kernel(
    const float* __restrict__ key, const float* __restrict__ Wk,
    const float* __restrict__ bk)
{
    __shared__ float As[16][64];
    __shared__ float Bs[16][32];
    gemm_nt_body(key, Wk, bk, g_kfull, blockIdx.y * 64, blockIdx.x * 32,
                 As, Bs, threadIdx.x);
}

// merged: blocks 0..383 -> vproj NT (value@Wv^T+bv), 384..767 -> ktil NN.
__global__ void __launch_bounds__(128) vktil_kernel(
    const float* __restrict__ value, const float* __restrict__ Wv,
    const float* __restrict__ bv, const float* __restrict__ Wq)
{
    __shared__ float As[16][64];
    __shared__ float Bs[16][32];
    int id = blockIdx.x;
    if (id < 384) {
        gemm_nt_body(value, Wv, bv, g_vfull,
                     (id / 24) * 64, (id % 24) * 32, As, Bs, threadIdx.x);
    } else {
        id -= 384;
        gemm_nn_body(g_kfull, Wq, g_ktil,
                     (id / 24) * 64, (id % 24) * 32, As, Bs, threadIdx.x);
    }
}

// ---------------------------------------------------------------------------
// g_c[r] = dot(g_kfull[r,:], bq)
// ---------------------------------------------------------------------------
__global__ void __launch_bounds__(256) bias_dot_kernel(const float* __restrict__ bq)
{
    int row  = blockIdx.x * 8 + (threadIdx.x >> 5);
    int lane = threadIdx.x & 31;
    const float* r = g_kfull + (size_t)row * DD;
    float acc = 0.f;
    #pragma unroll
    for (int j = 0; j < DD / 32; j++)
        acc += r[lane + 32 * j] * bq[lane + 32 * j];
    #pragma unroll
    for (int o = 16; o; o >>= 1) acc += __shfl_xor_sync(0xffffffffu, acc, o);
    if (lane == 0) g_c[row] = acc;
}

// ===========================================================================
// Fused attention: block = (t-pair, b). 256 threads, 8 warps.
// Chunks of 8 labels x 128 floats, double-buffered via cp.async.
// ===========================================================================
#define DCH 128                          // floats of D per chunk
#define NSUB (DD / DCH)                  // 6 sub-chunks per label group
#define NCH ((LL / 8) * NSUB)            // 48 chunks
#define STAGE_FLOATS (TG * 8 * DCH)      // 2048 floats = 8192 B
#define STAGE_BYTES  (STAGE_FLOATS * 4)

__device__ __forceinline__ void cp_async16(uint32_t dst, const void* src) {
    asm volatile("cp.async.cg.shared.global [%0], [%1], 16;\n" :: "r"(dst), "l"(src) : "memory");
}

__global__ void __launch_bounds__(256) attn_kernel(const float* __restrict__ query,
                                                   float* __restrict__ out)
{
    extern __shared__ float sq[];        // 2 * STAGE_FLOATS
    __shared__ float s_sc[TG][LL];
    __shared__ float s_attn[TG][LL];

    const int t0   = blockIdx.x * TG;
    const int b    = blockIdx.y;
    const int tid  = threadIdx.x;
    const int wid  = tid >> 5;
    const int lane = tid & 31;

    const float rs = 0.03608439182435161f;  // 1/sqrt(768)

    const uint32_t smq = (uint32_t)__cvta_generic_to_shared(sq);

    // cp.async mapping: 16 rows (TG*8) x 128 floats per chunk = 512 float4;
    // 256 threads -> 2 float4 each.
    const int tt_w  = tid >> 4;          // 0..15: row within chunk
    const int cw_tt = tt_w >> 3;         // t within group
    const int cw_w  = tt_w & 7;          // label within group of 8
    const int colb  = tid & 15;

    const float4* kb = (const float4*)g_ktil + (size_t)b * LL * (DD / 4);
    const size_t qrow0 = ((size_t)(b * TT + t0 + cw_tt) * LL + cw_w) * DD;

    float acc0 = 0.f, acc1 = 0.f;

    // issue chunk 0 (lg=0, h=0) into buffer 0
    {
        const float* src = query + qrow0;
        uint32_t dst = smq + (uint32_t)(tt_w * DCH * 4);
        cp_async16(dst + colb * 16, src + colb * 4);
        cp_async16(dst + (colb + 16) * 16, src + (colb + 16) * 4);
        asm volatile("cp.async.commit_group;\n" ::: "memory");
    }

    int lg = 0, h = 0;
    for (int c = 0; c < NCH; c++) {
        // decode next chunk and issue it
        if (c + 1 < NCH) {
            int hn = h + 1, lgn = lg;
            if (hn == NSUB) { hn = 0; lgn = lg + 1; }
            const float* src = query + qrow0 + (size_t)(lgn * 8) * DD + hn * DCH;
            uint32_t dst = smq + (uint32_t)(((c + 1) & 1) * STAGE_BYTES)
                               + (uint32_t)(tt_w * DCH * 4);
            cp_async16(dst + colb * 16, src + colb * 4);
            cp_async16(dst + (colb + 16) * 16, src + (colb + 16) * 4);
            asm volatile("cp.async.commit_group;\n" ::: "memory");
            asm volatile("cp.async.wait_group 1;\n" ::: "memory");
        } else {
            asm volatile("cp.async.wait_group 0;\n" ::: "memory");
        }
        __syncthreads();

        // compute buffer c&1: label l = lg*8 + wid, D slice [h*128, h*128+128)
        const int l = lg * 8 + wid;
        const float4* sq4 = (const float4*)(sq + (c & 1) * STAGE_FLOATS);
        float4 kv = kb[(size_t)l * 192 + h * 32 + lane];
        float4 q0 = sq4[(0 * 8 + wid) * 32 + lane];
        float4 q1 = sq4[(1 * 8 + wid) * 32 + lane];
        acc0 += q0.x * kv.x + q0.y * kv.y + q0.z * kv.z + q0.w * kv.w;
        acc1 += q1.x * kv.x + q1.y * kv.y + q1.z * kv.z + q1.w * kv.w;

        if (h == NSUB - 1) {
            float r0 = acc0, r1 = acc1;
            #pragma unroll
            for (int o = 16; o; o >>= 1) {
                r0 += __shfl_xor_sync(0xffffffffu, r0, o);
                r1 += __shfl_xor_sync(0xffffffffu, r1, o);
            }
            if (lane == 0) {
                float cc = g_c[b * LL + l];
                s_sc[0][l] = (r0 + cc) * rs;
                s_sc[1][l] = (r1 + cc) * rs;
            }
            acc0 = 0.f; acc1 = 0.f;
            h = 0; lg++;
        } else {
            h++;
        }
        __syncthreads();
    }

    // ---- softmax (warps 0..TG-1, one t each) ----
    if (wid < TG) {
        float v0 = s_sc[wid][lane], v1 = s_sc[wid][lane + 32];
        float m = fmaxf(v0, v1);
        #pragma unroll
        for (int o = 16; o; o >>= 1) m = fmaxf(m, __shfl_xor_sync(0xffffffffu, m, o));
        float e0 = expf(v0 - m), e1 = expf(v1 - m);
        float s = e0 + e1;
        #pragma unroll
        for (int o = 16; o; o >>= 1) s += __shfl_xor_sync(0xffffffffu, s, o);
        float inv = 1.f / s;
        s_attn[wid][lane]      = e0 * inv;
        s_attn[wid][lane + 32] = e1 * inv;
    }
    __syncthreads();

    // ---- output: read each v row once, write TG scaled rows ----
    const float4* vb = (const float4*)g_vfull + (size_t)b * LL * 192;
    #pragma unroll 1
    for (int l = wid; l < LL; l += 8) {
        const float4* vr = vb + (size_t)l * 192;
        float4 v0 = vr[lane], v1 = vr[lane + 32], v2 = vr[lane + 64],
               v3 = vr[lane + 96], v4 = vr[lane + 128], v5 = vr[lane + 160];
        #pragma unroll
        for (int tt = 0; tt < TG; tt++) {
            const float a = s_attn[tt][l];
            float4* orow = (float4*)out + ((size_t)(b * TT + t0 + tt) * LL + l) * 192;
            orow[lane]       = make_float4(a * v0.x, a * v0.y, a * v0.z, a * v0.w);
            orow[lane + 32]  = make_float4(a * v1.x, a * v1.y, a * v1.z, a * v1.w);
            orow[lane + 64]  = make_float4(a * v2.x, a * v2.y, a * v2.z, a * v2.w);
            orow[lane + 96]  = make_float4(a * v3.x, a * v3.y, a * v3.z, a * v3.w);
            orow[lane + 128] = make_float4(a * v4.x, a * v4.y, a * v4.z, a * v4.w);
            orow[lane + 160] = make_float4(a * v5.x, a * v5.y, a * v5.z, a * v5.w);
        }
    }
}

// ---------------------------------------------------------------------------
extern "C" void kernel_launch(void* const* d_in, const int* in_sizes, int n_in,
                              void* d_out, int out_size)
{
    const float* query = (const float*)d_in[0];
    const float* key   = (const float*)d_in[1];
    const float* value = (const float*)d_in[2];
    const float* Wq    = (const float*)d_in[3];
    const float* bq    = (const float*)d_in[4];
    const float* Wk    = (const float*)d_in[5];
    const float* bk    = (const float*)d_in[6];
    const float* Wv    = (const float*)d_in[7];
    const float* bv    = (const float*)d_in[8];
    float* out = (float*)d_out;

    keyproj_kernel<<<dim3(DD / 32, (BB * LL) / 64), 128>>>(key, Wk, bk);
    vktil_kernel<<<768, 128>>>(value, Wv, bv, Wq);
    bias_dot_kernel<<<(BB * LL) / 8, 256>>>(bq);
    attn_kernel<<<dim3(TT / TG, BB), 256, 2 * STAGE_BYTES>>>(query, out);
}